// round 8
// baseline (speedup 1.0000x reference)
#include <cuda_runtime.h>
#include <cstdint>
#include <cstddef>

// Problem constants
#define B_TOT   8192
#define D_IN    400
#define D_OUT   100
#define QD      10
#define NB      8            // batches per CTA (one warp each)
#define KC      50           // K chunk size
#define NCHUNK  (D_IN / KC)  // 8
#define THREADS 256

// Shared memory layout (floats)
#define WS_STRIDE 51                       // odd stride -> conflict-free both ways
#define WS_FLOATS (128 * WS_STRIDE)        // 6528 (rows 100..127 zero-padded)
#define XS_OFF    WS_FLOATS
#define XS_FLOATS (NB * KC * QD)           // 4000
#define SMEM_FLOATS (WS_FLOATS + XS_FLOATS) // 10528 floats = 42112 B

typedef unsigned long long u64;

__device__ __forceinline__ u64 pack2(float v) {
    u64 r;
    asm("mov.b64 %0, {%1, %1};" : "=l"(r) : "f"(v));
    return r;
}
__device__ __forceinline__ void ffma2(u64 &d, u64 a, u64 b) {
    // packed fp32x2 FMA (sm_100+): d = a*b + d  (two fp32 lanes)
    asm("fma.rn.f32x2 %0, %1, %2, %0;" : "+l"(d) : "l"(a), "l"(b));
}
__device__ __forceinline__ void unpack2(u64 v, float &lo, float &hi) {
    asm("mov.b64 {%0, %1}, %2;" : "=f"(lo), "=f"(hi) : "l"(v));
}

__global__ void __launch_bounds__(THREADS, 2)
proj_qr_kernel(const float* __restrict__ gX,
               const float* __restrict__ gW,
               float* __restrict__ gOut)
{
    __shared__ float sm[SMEM_FLOATS];

    const int tid  = threadIdx.x;
    const int lane = tid & 31;
    const int warp = tid >> 5;          // warp == local batch index (0..7)
    const int b0   = blockIdx.x * NB;

    // ------------------------------------------------------------------
    // Phase 1: GEMM  Y[b] = W @ X[b]   (each warp: one batch, lane owns
    // rows r = lane + 32*j, j=0..3; rows >= 100 stay exactly 0)
    // Accumulators: 4 rows x 5 q-pairs, packed f32x2.
    // ------------------------------------------------------------------
    u64 acc[4][5];
#pragma unroll
    for (int j = 0; j < 4; ++j)
#pragma unroll
        for (int p = 0; p < 5; ++p) acc[j][p] = 0ull;

    const float* Xc = sm + XS_OFF + warp * (KC * QD);

    for (int chunk = 0; chunk < NCHUNK; ++chunk) {
        const int k0 = chunk * KC;
        __syncthreads();   // previous chunk's smem reads done

        // Load W chunk: sm[o*51 + i] = W[o, k0+i]; o in [0,128), zero pad o>=100.
        // Consecutive tid -> consecutive i: coalesced LDG, conflict-free STS.
#pragma unroll
        for (int t = 0; t < (128 * KC) / THREADS; ++t) {   // 25 iters
            int idx = tid + t * THREADS;
            int o = idx / KC;
            int i = idx - o * KC;
            sm[o * WS_STRIDE + i] = (o < D_OUT) ? gW[o * D_IN + k0 + i] : 0.0f;
        }
        // Load X chunk: straight copy, 500 contiguous floats per batch.
        for (int idx = tid; idx < NB * KC * QD; idx += THREADS) {
            int b = idx / (KC * QD);
            int r = idx - b * (KC * QD);
            sm[XS_OFF + b * (KC * QD) + r] =
                gX[(size_t)(b0 + b) * (D_IN * QD) + (size_t)k0 * QD + r];
        }
        __syncthreads();

#pragma unroll 5
        for (int i = 0; i < KC; ++i) {
            u64 wp[4];
#pragma unroll
            for (int j = 0; j < 4; ++j)
                wp[j] = pack2(sm[(lane + 32 * j) * WS_STRIDE + i]);

            const u64* xp = reinterpret_cast<const u64*>(Xc + i * QD); // 8B aligned
            u64 xv[5];
#pragma unroll
            for (int p = 0; p < 5; ++p) xv[p] = xp[p];   // broadcast LDS.64

#pragma unroll
            for (int j = 0; j < 4; ++j)
#pragma unroll
                for (int p = 0; p < 5; ++p)
                    ffma2(acc[j][p], wp[j], xv[p]);
        }
    }
    __syncthreads();   // all warps done reading W/X smem (stage buffer reuse below)

    // Unpack Y into registers A[j][c]
    float A[4][QD];
#pragma unroll
    for (int j = 0; j < 4; ++j)
#pragma unroll
        for (int p = 0; p < 5; ++p)
            unpack2(acc[j][p], A[j][2 * p], A[j][2 * p + 1]);

    // ------------------------------------------------------------------
    // Phase 2: Householder QR (LAPACK slarfg convention) per warp.
    // Column k of A becomes v_k (zeros above diag, 1 at k, scaled tail).
    // ------------------------------------------------------------------
    const unsigned FULL = 0xffffffffu;
    float tau[QD];

#pragma unroll
    for (int k = 0; k < QD; ++k) {
        float alpha = __shfl_sync(FULL, A[0][k], k);   // row k lives in lane k, j=0
        float s = 0.0f;
#pragma unroll
        for (int j = 0; j < 4; ++j) {
            int r = lane + 32 * j;
            float v = A[j][k];
            s += (r > k) ? v * v : 0.0f;
        }
#pragma unroll
        for (int off = 16; off; off >>= 1) s += __shfl_xor_sync(FULL, s, off);

        float tk, inv;
        if (s == 0.0f) {            // zero tail -> tau = 0 (LAPACK), H = I
            tk = 0.0f; inv = 0.0f;
        } else {
            float nrm  = sqrtf(fmaf(alpha, alpha, s));
            float beta = (alpha >= 0.0f) ? -nrm : nrm;  // -sign(alpha)*||x||
            tk  = (beta - alpha) / beta;
            inv = 1.0f / (alpha - beta);
        }
        tau[k] = tk;

        // column k -> v_k  (v[k]=1, tail scaled, zeros above)
#pragma unroll
        for (int j = 0; j < 4; ++j) {
            int r = lane + 32 * j;
            float v = A[j][k];
            A[j][k] = (r == k) ? 1.0f : ((r > k) ? v * inv : 0.0f);
        }

        // trailing update: A[:,c] -= tau * (v^T A[:,c]) * v  for c > k
        float d[QD];
#pragma unroll
        for (int c = k + 1; c < QD; ++c) {
            float p = 0.0f;
#pragma unroll
            for (int j = 0; j < 4; ++j) p = fmaf(A[j][k], A[j][c], p);
            d[c] = p;
        }
#pragma unroll
        for (int off = 16; off; off >>= 1)
#pragma unroll
            for (int c = k + 1; c < QD; ++c)
                d[c] += __shfl_xor_sync(FULL, d[c], off);
#pragma unroll
        for (int c = k + 1; c < QD; ++c) {
            float w = tau[k] * d[c];
#pragma unroll
            for (int j = 0; j < 4; ++j)
                A[j][c] = fmaf(-w, A[j][k], A[j][c]);
        }
    }

    // ------------------------------------------------------------------
    // Phase 3: form Q = H_0 H_1 ... H_9 * [I_10 ; 0]   (sorgqr)
    // ------------------------------------------------------------------
    float Qm[4][QD];
#pragma unroll
    for (int j = 0; j < 4; ++j)
#pragma unroll
        for (int c = 0; c < QD; ++c)
            Qm[j][c] = ((lane + 32 * j) == c) ? 1.0f : 0.0f;

#pragma unroll
    for (int kk = QD - 1; kk >= 0; --kk) {
        float d[QD];
#pragma unroll
        for (int c = 0; c < QD; ++c) {
            float p = 0.0f;
#pragma unroll
            for (int j = 0; j < 4; ++j) p = fmaf(A[j][kk], Qm[j][c], p);
            d[c] = p;
        }
#pragma unroll
        for (int off = 16; off; off >>= 1)
#pragma unroll
            for (int c = 0; c < QD; ++c)
                d[c] += __shfl_xor_sync(FULL, d[c], off);
#pragma unroll
        for (int c = 0; c < QD; ++c) {
            float w = tau[kk] * d[c];
#pragma unroll
            for (int j = 0; j < 4; ++j)
                Qm[j][c] = fmaf(-w, A[j][kk], Qm[j][c]);
        }
    }

    // ------------------------------------------------------------------
    // Phase 4: stage Q in smem (per-warp disjoint 1000-float region) and
    // write coalesced to global.
    // ------------------------------------------------------------------
    float* stg = sm + warp * (D_OUT * QD);
#pragma unroll
    for (int j = 0; j < 4; ++j) {
        int r = lane + 32 * j;
        if (r < D_OUT) {
#pragma unroll
            for (int c = 0; c < QD; ++c)
                stg[r * QD + c] = Qm[j][c];
        }
    }
    __syncwarp();

    const size_t outBase = (size_t)(b0 + warp) * (D_OUT * QD);
    for (int idx = lane; idx < D_OUT * QD; idx += 32)
        gOut[outBase + idx] = stg[idx];
}

extern "C" void kernel_launch(void* const* d_in, const int* in_sizes, int n_in,
                              void* d_out, int out_size)
{
    const float* X = (const float*)d_in[0];   // (8192, 400, 10) fp32
    const float* W = (const float*)d_in[1];   // (100, 400) fp32
    float* out = (float*)d_out;               // (8192, 100, 10) fp32
    (void)in_sizes; (void)n_in; (void)out_size;

    proj_qr_kernel<<<B_TOT / NB, THREADS>>>(X, W, out);
}

// round 9
// speedup vs baseline: 1.0001x; 1.0001x over previous
#include <cuda_runtime.h>
#include <cstdint>
#include <cstddef>

// Problem constants
#define B_TOT   8192
#define D_IN    400
#define D_OUT   100
#define QD      10
#define NB      8            // batches per CTA (one warp each)
#define KC      50           // K chunk size
#define NCHUNK  (D_IN / KC)  // 8
#define THREADS 256

// Shared memory layout (floats)
#define WS_STRIDE 51                       // odd stride -> conflict-free both ways
#define WS_FLOATS (128 * WS_STRIDE)        // 6528 (rows 100..127 zero-padded)
#define XS_OFF    WS_FLOATS
#define XS_FLOATS (NB * KC * QD)           // 4000
#define SMEM_FLOATS (WS_FLOATS + XS_FLOATS) // 10528 floats = 42112 B

typedef unsigned long long u64;

__device__ __forceinline__ u64 pack2(float v) {
    u64 r;
    asm("mov.b64 %0, {%1, %1};" : "=l"(r) : "f"(v));
    return r;
}
__device__ __forceinline__ void ffma2(u64 &d, u64 a, u64 b) {
    // packed fp32x2 FMA (sm_100+): d = a*b + d  (two fp32 lanes)
    asm("fma.rn.f32x2 %0, %1, %2, %0;" : "+l"(d) : "l"(a), "l"(b));
}
__device__ __forceinline__ void unpack2(u64 v, float &lo, float &hi) {
    asm("mov.b64 {%0, %1}, %2;" : "=f"(lo), "=f"(hi) : "l"(v));
}

__global__ void __launch_bounds__(THREADS, 2)
proj_qr_kernel(const float* __restrict__ gX,
               const float* __restrict__ gW,
               float* __restrict__ gOut)
{
    __shared__ float sm[SMEM_FLOATS];

    const int tid  = threadIdx.x;
    const int lane = tid & 31;
    const int warp = tid >> 5;          // warp == local batch index (0..7)
    const int b0   = blockIdx.x * NB;

    // ------------------------------------------------------------------
    // Phase 1: GEMM  Y[b] = W @ X[b]   (each warp: one batch, lane owns
    // rows r = lane + 32*j, j=0..3; rows >= 100 stay exactly 0)
    // Accumulators: 4 rows x 5 q-pairs, packed f32x2.
    // ------------------------------------------------------------------
    u64 acc[4][5];
#pragma unroll
    for (int j = 0; j < 4; ++j)
#pragma unroll
        for (int p = 0; p < 5; ++p) acc[j][p] = 0ull;

    const float* Xc = sm + XS_OFF + warp * (KC * QD);

    for (int chunk = 0; chunk < NCHUNK; ++chunk) {
        const int k0 = chunk * KC;
        __syncthreads();   // previous chunk's smem reads done

        // Load W chunk: sm[o*51 + i] = W[o, k0+i]; o in [0,128), zero pad o>=100.
        // Consecutive tid -> consecutive i: coalesced LDG, conflict-free STS.
#pragma unroll
        for (int t = 0; t < (128 * KC) / THREADS; ++t) {   // 25 iters
            int idx = tid + t * THREADS;
            int o = idx / KC;
            int i = idx - o * KC;
            sm[o * WS_STRIDE + i] = (o < D_OUT) ? gW[o * D_IN + k0 + i] : 0.0f;
        }
        // Load X chunk: straight copy, 500 contiguous floats per batch.
        for (int idx = tid; idx < NB * KC * QD; idx += THREADS) {
            int b = idx / (KC * QD);
            int r = idx - b * (KC * QD);
            sm[XS_OFF + b * (KC * QD) + r] =
                gX[(size_t)(b0 + b) * (D_IN * QD) + (size_t)k0 * QD + r];
        }
        __syncthreads();

#pragma unroll 5
        for (int i = 0; i < KC; ++i) {
            u64 wp[4];
#pragma unroll
            for (int j = 0; j < 4; ++j)
                wp[j] = pack2(sm[(lane + 32 * j) * WS_STRIDE + i]);

            const u64* xp = reinterpret_cast<const u64*>(Xc + i * QD); // 8B aligned
            u64 xv[5];
#pragma unroll
            for (int p = 0; p < 5; ++p) xv[p] = xp[p];   // broadcast LDS.64

#pragma unroll
            for (int j = 0; j < 4; ++j)
#pragma unroll
                for (int p = 0; p < 5; ++p)
                    ffma2(acc[j][p], wp[j], xv[p]);
        }
    }
    __syncthreads();   // all warps done reading W/X smem (stage buffer reuse below)

    // Unpack Y into registers A[j][c]
    float A[4][QD];
#pragma unroll
    for (int j = 0; j < 4; ++j)
#pragma unroll
        for (int p = 0; p < 5; ++p)
            unpack2(acc[j][p], A[j][2 * p], A[j][2 * p + 1]);

    // ------------------------------------------------------------------
    // Phase 2: Householder QR (LAPACK slarfg convention) per warp.
    // Column k of A becomes v_k (zeros above diag, 1 at k, scaled tail).
    // ------------------------------------------------------------------
    const unsigned FULL = 0xffffffffu;
    float tau[QD];

#pragma unroll
    for (int k = 0; k < QD; ++k) {
        float alpha = __shfl_sync(FULL, A[0][k], k);   // row k lives in lane k, j=0
        float s = 0.0f;
#pragma unroll
        for (int j = 0; j < 4; ++j) {
            int r = lane + 32 * j;
            float v = A[j][k];
            s += (r > k) ? v * v : 0.0f;
        }
#pragma unroll
        for (int off = 16; off; off >>= 1) s += __shfl_xor_sync(FULL, s, off);

        float tk, inv;
        if (s == 0.0f) {            // zero tail -> tau = 0 (LAPACK), H = I
            tk = 0.0f; inv = 0.0f;
        } else {
            float nrm  = sqrtf(fmaf(alpha, alpha, s));
            float beta = (alpha >= 0.0f) ? -nrm : nrm;  // -sign(alpha)*||x||
            tk  = (beta - alpha) / beta;
            inv = 1.0f / (alpha - beta);
        }
        tau[k] = tk;

        // column k -> v_k  (v[k]=1, tail scaled, zeros above)
#pragma unroll
        for (int j = 0; j < 4; ++j) {
            int r = lane + 32 * j;
            float v = A[j][k];
            A[j][k] = (r == k) ? 1.0f : ((r > k) ? v * inv : 0.0f);
        }

        // trailing update: A[:,c] -= tau * (v^T A[:,c]) * v  for c > k
        float d[QD];
#pragma unroll
        for (int c = k + 1; c < QD; ++c) {
            float p = 0.0f;
#pragma unroll
            for (int j = 0; j < 4; ++j) p = fmaf(A[j][k], A[j][c], p);
            d[c] = p;
        }
#pragma unroll
        for (int off = 16; off; off >>= 1)
#pragma unroll
            for (int c = k + 1; c < QD; ++c)
                d[c] += __shfl_xor_sync(FULL, d[c], off);
#pragma unroll
        for (int c = k + 1; c < QD; ++c) {
            float w = tau[k] * d[c];
#pragma unroll
            for (int j = 0; j < 4; ++j)
                A[j][c] = fmaf(-w, A[j][k], A[j][c]);
        }
    }

    // ------------------------------------------------------------------
    // Phase 3: form Q = H_0 H_1 ... H_9 * [I_10 ; 0]   (sorgqr)
    // ------------------------------------------------------------------
    float Qm[4][QD];
#pragma unroll
    for (int j = 0; j < 4; ++j)
#pragma unroll
        for (int c = 0; c < QD; ++c)
            Qm[j][c] = ((lane + 32 * j) == c) ? 1.0f : 0.0f;

#pragma unroll
    for (int kk = QD - 1; kk >= 0; --kk) {
        float d[QD];
#pragma unroll
        for (int c = 0; c < QD; ++c) {
            float p = 0.0f;
#pragma unroll
            for (int j = 0; j < 4; ++j) p = fmaf(A[j][kk], Qm[j][c], p);
            d[c] = p;
        }
#pragma unroll
        for (int off = 16; off; off >>= 1)
#pragma unroll
            for (int c = 0; c < QD; ++c)
                d[c] += __shfl_xor_sync(FULL, d[c], off);
#pragma unroll
        for (int c = 0; c < QD; ++c) {
            float w = tau[kk] * d[c];
#pragma unroll
            for (int j = 0; j < 4; ++j)
                Qm[j][c] = fmaf(-w, A[j][kk], Qm[j][c]);
        }
    }

    // ------------------------------------------------------------------
    // Phase 4: stage Q in smem (per-warp disjoint 1000-float region) and
    // write coalesced to global.
    // ------------------------------------------------------------------
    float* stg = sm + warp * (D_OUT * QD);
#pragma unroll
    for (int j = 0; j < 4; ++j) {
        int r = lane + 32 * j;
        if (r < D_OUT) {
#pragma unroll
            for (int c = 0; c < QD; ++c)
                stg[r * QD + c] = Qm[j][c];
        }
    }
    __syncwarp();

    const size_t outBase = (size_t)(b0 + warp) * (D_OUT * QD);
    for (int idx = lane; idx < D_OUT * QD; idx += 32)
        gOut[outBase + idx] = stg[idx];
}

extern "C" void kernel_launch(void* const* d_in, const int* in_sizes, int n_in,
                              void* d_out, int out_size)
{
    const float* X = (const float*)d_in[0];   // (8192, 400, 10) fp32
    const float* W = (const float*)d_in[1];   // (100, 400) fp32
    float* out = (float*)d_out;               // (8192, 100, 10) fp32
    (void)in_sizes; (void)n_in; (void)out_size;

    proj_qr_kernel<<<B_TOT / NB, THREADS>>>(X, W, out);
}